// round 1
// baseline (speedup 1.0000x reference)
#include <cuda_runtime.h>
#include <math_constants.h>

static constexpr int NMAX = 50000;
static constexpr int EMAX = 800000;
static constexpr int C    = 256;   // channels per node at every stage

// ---------------- scratch (static device arrays; no allocation) -------------
__device__ float g_h0[(size_t)NMAX * C];
__device__ float g_x1[(size_t)NMAX * C];
__device__ float g_h1[(size_t)NMAX * C];
__device__ float g_el0[NMAX * 2];
__device__ float g_er0[NMAX * 2];
__device__ float g_el1[NMAX];
__device__ float g_er1[NMAX];
__device__ int   g_cnt[NMAX];
__device__ int   g_rowptr[NMAX + 1];
__device__ int   g_cursor[NMAX];
__device__ int   g_perm[EMAX];

// ---------------- CSR build -------------------------------------------------
__global__ void k_hist(const int* __restrict__ dst, int E) {
    int i = blockIdx.x * blockDim.x + threadIdx.x;
    if (i < E) atomicAdd(&g_cnt[dst[i]], 1);
}

// single block, 1024 threads: chunked exclusive scan of g_cnt -> rowptr/cursor
__global__ void k_scan(int N) {
    const int T = 1024;
    int tid = threadIdx.x;
    int per = (N + T - 1) / T;
    int begin = tid * per;
    int end   = min(begin + per, N);
    int sum = 0;
    for (int i = begin; i < end; i++) sum += g_cnt[i];
    __shared__ int s[T];
    s[tid] = sum;
    __syncthreads();
    for (int off = 1; off < T; off <<= 1) {
        int v = (tid >= off) ? s[tid - off] : 0;
        __syncthreads();
        s[tid] += v;
        __syncthreads();
    }
    int run = s[tid] - sum;  // exclusive prefix for my chunk
    for (int i = begin; i < end; i++) {
        g_rowptr[i] = run;
        g_cursor[i] = run;
        run += g_cnt[i];
    }
    if (tid == T - 1) g_rowptr[N] = s[T - 1];
}

__global__ void k_scatter(const int* __restrict__ dst, int E) {
    int i = blockIdx.x * blockDim.x + threadIdx.x;
    if (i < E) {
        int p = atomicAdd(&g_cursor[dst[i]], 1);
        g_perm[p] = i;
    }
}

// ---------------- fp32 SGEMM: C[M,N] = A[M,K] @ B[K,N] ----------------------
// BM=BN=128, BK=8, 256 threads, 8x8 per thread. N,K multiples of 8/4; M guarded.
__global__ void __launch_bounds__(256) k_sgemm(const float* __restrict__ A,
                                               const float* __restrict__ B,
                                               float* __restrict__ Cm,
                                               int M, int N, int K) {
    __shared__ float As[8][128];
    __shared__ float Bs[8][128];
    int tid = threadIdx.x;
    int bn0 = blockIdx.x * 128;
    int m0  = blockIdx.y * 128;
    int ty = tid >> 4, tx = tid & 15;
    int arow = tid >> 1, acol = (tid & 1) * 4;
    int brow = tid >> 5, bcol = (tid & 31) * 4;

    float acc[8][8];
#pragma unroll
    for (int i = 0; i < 8; i++)
#pragma unroll
        for (int j = 0; j < 8; j++) acc[i][j] = 0.f;

    for (int k0 = 0; k0 < K; k0 += 8) {
        int grow = m0 + arow;
        float4 va = make_float4(0.f, 0.f, 0.f, 0.f);
        if (grow < M) va = *(const float4*)(A + (size_t)grow * K + k0 + acol);
        As[acol + 0][arow] = va.x;
        As[acol + 1][arow] = va.y;
        As[acol + 2][arow] = va.z;
        As[acol + 3][arow] = va.w;
        float4 vb = *(const float4*)(B + (size_t)(k0 + brow) * N + bn0 + bcol);
        *(float4*)&Bs[brow][bcol] = vb;
        __syncthreads();
#pragma unroll
        for (int k = 0; k < 8; k++) {
            float ra[8], rb[8];
#pragma unroll
            for (int i = 0; i < 8; i++) ra[i] = As[k][ty * 8 + i];
#pragma unroll
            for (int j = 0; j < 8; j++) rb[j] = Bs[k][tx * 8 + j];
#pragma unroll
            for (int i = 0; i < 8; i++)
#pragma unroll
                for (int j = 0; j < 8; j++)
                    acc[i][j] = fmaf(ra[i], rb[j], acc[i][j]);
        }
        __syncthreads();
    }
#pragma unroll
    for (int i = 0; i < 8; i++) {
        int row = m0 + ty * 8 + i;
        if (row < M) {
            float4 o1 = make_float4(acc[i][0], acc[i][1], acc[i][2], acc[i][3]);
            float4 o2 = make_float4(acc[i][4], acc[i][5], acc[i][6], acc[i][7]);
            *(float4*)(Cm + (size_t)row * N + bn0 + tx * 8)     = o1;
            *(float4*)(Cm + (size_t)row * N + bn0 + tx * 8 + 4) = o2;
        }
    }
}

// ---------------- per-node attention logits el/er ---------------------------
// h layout: [N][H*DOUT] flattened, channel t -> head t/DOUT. al/ar flattened [H*DOUT].
template <int H>
__global__ void __launch_bounds__(256) k_elr(const float* __restrict__ h,
                                             const float* __restrict__ al,
                                             const float* __restrict__ ar,
                                             float* __restrict__ el,
                                             float* __restrict__ er) {
    constexpr int G = C / H;
    int n = blockIdx.x, t = threadIdx.x;
    float v  = h[(size_t)n * C + t];
    float pl = v * al[t];
    float pr = v * ar[t];
    __shared__ float sl[C];
    __shared__ float sr[C];
    sl[t] = pl;
    sr[t] = pr;
    __syncthreads();
#pragma unroll
    for (int off = G / 2; off > 0; off >>= 1) {
        if ((t % G) < off) {
            sl[t] += sl[t + off];
            sr[t] += sr[t + off];
        }
        __syncthreads();
    }
    if ((t % G) == 0) {
        el[n * H + t / G] = sl[t];
        er[n * H + t / G] = sr[t];
    }
}

// ---------------- edge-softmax + aggregation (one block per dst node) -------
template <int H>
__global__ void __launch_bounds__(256) k_aggregate(
    const float* __restrict__ hmat, const float* __restrict__ el,
    const float* __restrict__ er, const float* __restrict__ bias,
    const int* __restrict__ rowptr, const int* __restrict__ perm,
    const int* __restrict__ srcarr, float* __restrict__ out,
    int relu_out, int zero0) {
    constexpr int DOUT  = C / H;
    constexpr int CHUNK = 256;
    int n   = blockIdx.x;
    int tid = threadIdx.x;
    int start = rowptr[n];
    int deg   = rowptr[n + 1] - start;

    __shared__ int   s_src[CHUNK];
    __shared__ float s_coef[CHUNK * H];
    __shared__ float s_warp[8 * H];
    __shared__ float s_m[H];
    __shared__ float s_sum[H];

    float ern[H];
#pragma unroll
    for (int h = 0; h < H; h++) ern[h] = er[n * H + h];

    // ---- pass 1: segment max of leaky_relu(el[src]+er[n]) ----
    float mx[H];
#pragma unroll
    for (int h = 0; h < H; h++) mx[h] = -CUDART_INF_F;
    for (int i = tid; i < deg; i += 256) {
        int e = perm[start + i];
        int s = srcarr[e];
#pragma unroll
        for (int h = 0; h < H; h++) {
            float v = el[s * H + h] + ern[h];
            v = v > 0.f ? v : 0.2f * v;
            mx[h] = fmaxf(mx[h], v);
        }
    }
#pragma unroll
    for (int h = 0; h < H; h++)
        for (int o = 16; o > 0; o >>= 1)
            mx[h] = fmaxf(mx[h], __shfl_xor_sync(0xffffffffu, mx[h], o));
    if ((tid & 31) == 0)
#pragma unroll
        for (int h = 0; h < H; h++) s_warp[(tid >> 5) * H + h] = mx[h];
    __syncthreads();
    if (tid == 0) {
#pragma unroll
        for (int h = 0; h < H; h++) {
            float v = -CUDART_INF_F;
            for (int w = 0; w < 8; w++) v = fmaxf(v, s_warp[w * H + h]);
            s_m[h] = v;
        }
    }
    __syncthreads();
    float m[H];
#pragma unroll
    for (int h = 0; h < H; h++) m[h] = s_m[h];

    // ---- pass 2: segment sum of exp(e - m) ----
    float sm[H];
#pragma unroll
    for (int h = 0; h < H; h++) sm[h] = 0.f;
    for (int i = tid; i < deg; i += 256) {
        int e = perm[start + i];
        int s = srcarr[e];
#pragma unroll
        for (int h = 0; h < H; h++) {
            float v = el[s * H + h] + ern[h];
            v = v > 0.f ? v : 0.2f * v;
            sm[h] += __expf(v - m[h]);
        }
    }
#pragma unroll
    for (int h = 0; h < H; h++)
        for (int o = 16; o > 0; o >>= 1)
            sm[h] += __shfl_xor_sync(0xffffffffu, sm[h], o);
    if ((tid & 31) == 0)
#pragma unroll
        for (int h = 0; h < H; h++) s_warp[(tid >> 5) * H + h] = sm[h];
    __syncthreads();
    if (tid == 0) {
#pragma unroll
        for (int h = 0; h < H; h++) {
            float v = 0.f;
            for (int w = 0; w < 8; w++) v += s_warp[w * H + h];
            s_sum[h] = v;
        }
    }
    __syncthreads();
    float inv[H];
#pragma unroll
    for (int h = 0; h < H; h++) {
        float sv = s_sum[h];
        inv[h] = sv > 0.f ? 1.f / sv : 0.f;
    }

    // ---- pass 3: out[c] = sum_e coef_e * h[src_e][c] ----
    float acc = 0.f;
    int hof = tid / DOUT;
    for (int base = 0; base < deg; base += CHUNK) {
        int cnt = min(CHUNK, deg - base);
        __syncthreads();
        if (tid < cnt) {
            int e = perm[start + base + tid];
            int s = srcarr[e];
            s_src[tid] = s;
#pragma unroll
            for (int h = 0; h < H; h++) {
                float v = el[s * H + h] + ern[h];
                v = v > 0.f ? v : 0.2f * v;
                s_coef[tid * H + h] = __expf(v - m[h]) * inv[h];
            }
        }
        __syncthreads();
#pragma unroll 4
        for (int j = 0; j < cnt; j++) {
            acc = fmaf(s_coef[j * H + hof], hmat[(size_t)s_src[j] * C + tid], acc);
        }
    }

    float o = acc + bias[tid];
    if (relu_out) o = fmaxf(o, 0.f);
    if (zero0 && n == 0) o = 0.f;
    out[(size_t)n * C + tid] = o;
}

// ---------------- host launcher ----------------------------------------------
extern "C" void kernel_launch(void* const* d_in, const int* in_sizes, int n_in,
                              void* d_out, int out_size) {
    const float* emb = (const float*)d_in[0];
    const float* W0  = (const float*)d_in[1];
    const float* al0 = (const float*)d_in[2];
    const float* ar0 = (const float*)d_in[3];
    const float* b0  = (const float*)d_in[4];
    const float* W1  = (const float*)d_in[5];
    const float* al1 = (const float*)d_in[6];
    const float* ar1 = (const float*)d_in[7];
    const float* b1  = (const float*)d_in[8];
    const int*   src = (const int*)d_in[9];
    const int*   dst = (const int*)d_in[10];
    float* out = (float*)d_out;

    int numNodes = in_sizes[0] / 128;   // 50000
    int E        = in_sizes[9];         // 800000

    float *h0, *x1, *h1, *el0, *er0, *el1, *er1;
    int *cnt, *rowptr, *perm;
    cudaGetSymbolAddress((void**)&h0, g_h0);
    cudaGetSymbolAddress((void**)&x1, g_x1);
    cudaGetSymbolAddress((void**)&h1, g_h1);
    cudaGetSymbolAddress((void**)&el0, g_el0);
    cudaGetSymbolAddress((void**)&er0, g_er0);
    cudaGetSymbolAddress((void**)&el1, g_el1);
    cudaGetSymbolAddress((void**)&er1, g_er1);
    cudaGetSymbolAddress((void**)&cnt, g_cnt);
    cudaGetSymbolAddress((void**)&rowptr, g_rowptr);
    cudaGetSymbolAddress((void**)&perm, g_perm);

    // CSR build (shared by both layers)
    cudaMemsetAsync(cnt, 0, numNodes * sizeof(int));
    k_hist<<<(E + 255) / 256, 256>>>(dst, E);
    k_scan<<<1, 1024>>>(numNodes);
    k_scatter<<<(E + 255) / 256, 256>>>(dst, E);

    // layer 0
    k_sgemm<<<dim3(2, (numNodes + 127) / 128), 256>>>(emb, W0, h0, numNodes, 256, 128);
    k_elr<2><<<numNodes, 256>>>(h0, al0, ar0, el0, er0);
    k_aggregate<2><<<numNodes, 256>>>(h0, el0, er0, b0, rowptr, perm, src, x1, 1, 0);

    // layer 1
    k_sgemm<<<dim3(2, (numNodes + 127) / 128), 256>>>(x1, W1, h1, numNodes, 256, 256);
    k_elr<1><<<numNodes, 256>>>(h1, al1, ar1, el1, er1);
    k_aggregate<1><<<numNodes, 256>>>(h1, el1, er1, b1, rowptr, perm, src, out, 0, 1);
}

// round 2
// speedup vs baseline: 1.1187x; 1.1187x over previous
#include <cuda_runtime.h>
#include <math_constants.h>

static constexpr int NMAX = 50000;
static constexpr int EMAX = 800000;
static constexpr int C    = 256;   // channels per node at every stage

// ---------------- scratch (static device arrays; no allocation) -------------
__device__ float g_h0[(size_t)NMAX * C];
__device__ float g_x1[(size_t)NMAX * C];
__device__ float g_h1[(size_t)NMAX * C];
__device__ float g_el0[NMAX * 2];
__device__ float g_er0[NMAX * 2];
__device__ float g_el1[NMAX];
__device__ float g_er1[NMAX];
__device__ float g_m[NMAX * 2];
__device__ float g_is[NMAX * 2];
__device__ float g_alpha[(size_t)EMAX * 2];
__device__ int   g_cnt[NMAX];
__device__ int   g_rowptr[NMAX + 1];
__device__ int   g_cursor[NMAX];
__device__ int   g_srcp[EMAX];   // src id per permuted edge slot
__device__ int   g_dstp[EMAX];   // dst id per permuted edge slot

// ---------------- CSR build -------------------------------------------------
__global__ void k_hist(const int* __restrict__ dst, int E) {
    int i = blockIdx.x * blockDim.x + threadIdx.x;
    if (i < E) atomicAdd(&g_cnt[dst[i]], 1);
}

// single block, 1024 threads: chunked exclusive scan of g_cnt -> rowptr/cursor
__global__ void k_scan(int N) {
    const int T = 1024;
    int tid = threadIdx.x;
    int per = (N + T - 1) / T;
    int begin = tid * per;
    int end   = min(begin + per, N);
    int sum = 0;
    for (int i = begin; i < end; i++) sum += g_cnt[i];
    __shared__ int s[T];
    s[tid] = sum;
    __syncthreads();
    for (int off = 1; off < T; off <<= 1) {
        int v = (tid >= off) ? s[tid - off] : 0;
        __syncthreads();
        s[tid] += v;
        __syncthreads();
    }
    int run = s[tid] - sum;  // exclusive prefix for my chunk
    for (int i = begin; i < end; i++) {
        g_rowptr[i] = run;
        g_cursor[i] = run;
        run += g_cnt[i];
    }
    if (tid == T - 1) g_rowptr[N] = s[T - 1];
}

__global__ void k_scatter(const int* __restrict__ src, const int* __restrict__ dst, int E) {
    int i = blockIdx.x * blockDim.x + threadIdx.x;
    if (i < E) {
        int d = dst[i];
        int p = atomicAdd(&g_cursor[d], 1);
        g_srcp[p] = src[i];
        g_dstp[p] = d;
    }
}

// ---------------- fp32 SGEMM: C[M,N] = A[M,K] @ B[K,N] ----------------------
__global__ void __launch_bounds__(256) k_sgemm(const float* __restrict__ A,
                                               const float* __restrict__ B,
                                               float* __restrict__ Cm,
                                               int M, int N, int K) {
    __shared__ float As[8][128];
    __shared__ float Bs[8][128];
    int tid = threadIdx.x;
    int bn0 = blockIdx.x * 128;
    int m0  = blockIdx.y * 128;
    int ty = tid >> 4, tx = tid & 15;
    int arow = tid >> 1, acol = (tid & 1) * 4;
    int brow = tid >> 5, bcol = (tid & 31) * 4;

    float acc[8][8];
#pragma unroll
    for (int i = 0; i < 8; i++)
#pragma unroll
        for (int j = 0; j < 8; j++) acc[i][j] = 0.f;

    for (int k0 = 0; k0 < K; k0 += 8) {
        int grow = m0 + arow;
        float4 va = make_float4(0.f, 0.f, 0.f, 0.f);
        if (grow < M) va = *(const float4*)(A + (size_t)grow * K + k0 + acol);
        As[acol + 0][arow] = va.x;
        As[acol + 1][arow] = va.y;
        As[acol + 2][arow] = va.z;
        As[acol + 3][arow] = va.w;
        float4 vb = *(const float4*)(B + (size_t)(k0 + brow) * N + bn0 + bcol);
        *(float4*)&Bs[brow][bcol] = vb;
        __syncthreads();
#pragma unroll
        for (int k = 0; k < 8; k++) {
            float ra[8], rb[8];
#pragma unroll
            for (int i = 0; i < 8; i++) ra[i] = As[k][ty * 8 + i];
#pragma unroll
            for (int j = 0; j < 8; j++) rb[j] = Bs[k][tx * 8 + j];
#pragma unroll
            for (int i = 0; i < 8; i++)
#pragma unroll
                for (int j = 0; j < 8; j++)
                    acc[i][j] = fmaf(ra[i], rb[j], acc[i][j]);
        }
        __syncthreads();
    }
#pragma unroll
    for (int i = 0; i < 8; i++) {
        int row = m0 + ty * 8 + i;
        if (row < M) {
            float4 o1 = make_float4(acc[i][0], acc[i][1], acc[i][2], acc[i][3]);
            float4 o2 = make_float4(acc[i][4], acc[i][5], acc[i][6], acc[i][7]);
            *(float4*)(Cm + (size_t)row * N + bn0 + tx * 8)     = o1;
            *(float4*)(Cm + (size_t)row * N + bn0 + tx * 8 + 4) = o2;
        }
    }
}

// ---------------- per-node attention logits el/er ---------------------------
template <int H>
__global__ void __launch_bounds__(256) k_elr(const float* __restrict__ h,
                                             const float* __restrict__ al,
                                             const float* __restrict__ ar,
                                             float* __restrict__ el,
                                             float* __restrict__ er) {
    constexpr int G = C / H;
    int n = blockIdx.x, t = threadIdx.x;
    float v  = h[(size_t)n * C + t];
    float pl = v * al[t];
    float pr = v * ar[t];
    __shared__ float sl[C];
    __shared__ float sr[C];
    sl[t] = pl;
    sr[t] = pr;
    __syncthreads();
#pragma unroll
    for (int off = G / 2; off > 0; off >>= 1) {
        if ((t % G) < off) {
            sl[t] += sl[t + off];
            sr[t] += sr[t + off];
        }
        __syncthreads();
    }
    if ((t % G) == 0) {
        el[n * H + t / G] = sl[t];
        er[n * H + t / G] = sr[t];
    }
}

// ---------------- phase A: per-node softmax stats (warp per node) -----------
// online softmax over incoming edges: m[n][h], inv_s[n][h]
template <int H>
__global__ void __launch_bounds__(256) k_stats(const float* __restrict__ el,
                                               const float* __restrict__ er,
                                               const int* __restrict__ rowptr,
                                               const int* __restrict__ srcp,
                                               float* __restrict__ mOut,
                                               float* __restrict__ isOut,
                                               int N) {
    int warp = (blockIdx.x * blockDim.x + threadIdx.x) >> 5;
    int lane = threadIdx.x & 31;
    if (warp >= N) return;
    int n = warp;
    int start = rowptr[n];
    int deg   = rowptr[n + 1] - start;

    float ern[H];
#pragma unroll
    for (int h = 0; h < H; h++) ern[h] = er[n * H + h];

    float m[H], s[H];
#pragma unroll
    for (int h = 0; h < H; h++) { m[h] = -1e30f; s[h] = 0.f; }

    for (int i = lane; i < deg; i += 32) {
        int sid = srcp[start + i];
#pragma unroll
        for (int h = 0; h < H; h++) {
            float v = el[sid * H + h] + ern[h];
            v = v > 0.f ? v : 0.2f * v;
            float mn = fmaxf(m[h], v);
            s[h] = s[h] * __expf(m[h] - mn) + __expf(v - mn);
            m[h] = mn;
        }
    }
#pragma unroll
    for (int h = 0; h < H; h++) {
#pragma unroll
        for (int o = 16; o > 0; o >>= 1) {
            float m2 = __shfl_xor_sync(0xffffffffu, m[h], o);
            float s2 = __shfl_xor_sync(0xffffffffu, s[h], o);
            float mn = fmaxf(m[h], m2);
            s[h] = s[h] * __expf(m[h] - mn) + s2 * __expf(m2 - mn);
            m[h] = mn;
        }
    }
    if (lane == 0) {
#pragma unroll
        for (int h = 0; h < H; h++) {
            mOut[n * H + h]  = m[h];
            isOut[n * H + h] = s[h] > 0.f ? 1.f / s[h] : 0.f;
        }
    }
}

// ---------------- phase B: per-edge alpha (permuted order) ------------------
template <int H>
__global__ void __launch_bounds__(256) k_alpha(const float* __restrict__ el,
                                               const float* __restrict__ er,
                                               const float* __restrict__ mIn,
                                               const float* __restrict__ isIn,
                                               const int* __restrict__ srcp,
                                               const int* __restrict__ dstp,
                                               float* __restrict__ alpha,
                                               int E) {
    int i = blockIdx.x * blockDim.x + threadIdx.x;
    if (i >= E) return;
    int sid = srcp[i];
    int d   = dstp[i];
#pragma unroll
    for (int h = 0; h < H; h++) {
        float v = el[sid * H + h] + er[d * H + h];
        v = v > 0.f ? v : 0.2f * v;
        alpha[(size_t)i * H + h] = __expf(v - mIn[d * H + h]) * isIn[d * H + h];
    }
}

// ---------------- phase C: aggregation gather (block per node) --------------
template <int H>
__global__ void __launch_bounds__(256) k_gather(const float* __restrict__ hmat,
                                                const float* __restrict__ alpha,
                                                const float* __restrict__ bias,
                                                const int* __restrict__ rowptr,
                                                const int* __restrict__ srcp,
                                                float* __restrict__ out,
                                                int relu_out, int zero0) {
    constexpr int DOUT  = C / H;
    constexpr int CHUNK = 256;
    int n   = blockIdx.x;
    int tid = threadIdx.x;
    int start = rowptr[n];
    int deg   = rowptr[n + 1] - start;

    __shared__ int   s_src[CHUNK];
    __shared__ float s_a[CHUNK * H];

    float acc = 0.f;
    int hof = tid / DOUT;
    for (int base = 0; base < deg; base += CHUNK) {
        int cnt = min(CHUNK, deg - base);
        if (base) __syncthreads();
        if (tid < cnt) {
            int idx = start + base + tid;
            s_src[tid] = srcp[idx];
#pragma unroll
            for (int h = 0; h < H; h++)
                s_a[tid * H + h] = alpha[(size_t)idx * H + h];
        }
        __syncthreads();
#pragma unroll 4
        for (int j = 0; j < cnt; j++) {
            acc = fmaf(s_a[j * H + hof], hmat[(size_t)s_src[j] * C + tid], acc);
        }
    }

    float o = acc + bias[tid];
    if (relu_out) o = fmaxf(o, 0.f);
    if (zero0 && n == 0) o = 0.f;
    out[(size_t)n * C + tid] = o;
}

// ---------------- host launcher ----------------------------------------------
extern "C" void kernel_launch(void* const* d_in, const int* in_sizes, int n_in,
                              void* d_out, int out_size) {
    const float* emb = (const float*)d_in[0];
    const float* W0  = (const float*)d_in[1];
    const float* al0 = (const float*)d_in[2];
    const float* ar0 = (const float*)d_in[3];
    const float* b0  = (const float*)d_in[4];
    const float* W1  = (const float*)d_in[5];
    const float* al1 = (const float*)d_in[6];
    const float* ar1 = (const float*)d_in[7];
    const float* b1  = (const float*)d_in[8];
    const int*   src = (const int*)d_in[9];
    const int*   dst = (const int*)d_in[10];
    float* out = (float*)d_out;

    int numNodes = in_sizes[0] / 128;   // 50000
    int E        = in_sizes[9];         // 800000

    float *h0, *x1, *h1, *el0, *er0, *el1, *er1, *mbuf, *isbuf, *alpha;
    int *cnt, *rowptr, *srcp, *dstp;
    cudaGetSymbolAddress((void**)&h0, g_h0);
    cudaGetSymbolAddress((void**)&x1, g_x1);
    cudaGetSymbolAddress((void**)&h1, g_h1);
    cudaGetSymbolAddress((void**)&el0, g_el0);
    cudaGetSymbolAddress((void**)&er0, g_er0);
    cudaGetSymbolAddress((void**)&el1, g_el1);
    cudaGetSymbolAddress((void**)&er1, g_er1);
    cudaGetSymbolAddress((void**)&mbuf, g_m);
    cudaGetSymbolAddress((void**)&isbuf, g_is);
    cudaGetSymbolAddress((void**)&alpha, g_alpha);
    cudaGetSymbolAddress((void**)&cnt, g_cnt);
    cudaGetSymbolAddress((void**)&rowptr, g_rowptr);
    cudaGetSymbolAddress((void**)&srcp, g_srcp);
    cudaGetSymbolAddress((void**)&dstp, g_dstp);

    // CSR build (shared by both layers)
    cudaMemsetAsync(cnt, 0, numNodes * sizeof(int));
    k_hist<<<(E + 255) / 256, 256>>>(dst, E);
    k_scan<<<1, 1024>>>(numNodes);
    k_scatter<<<(E + 255) / 256, 256>>>(src, dst, E);

    int statBlocks = (numNodes * 32 + 255) / 256;

    // layer 0 (H=2)
    k_sgemm<<<dim3(2, (numNodes + 127) / 128), 256>>>(emb, W0, h0, numNodes, 256, 128);
    k_elr<2><<<numNodes, 256>>>(h0, al0, ar0, el0, er0);
    k_stats<2><<<statBlocks, 256>>>(el0, er0, rowptr, srcp, mbuf, isbuf, numNodes);
    k_alpha<2><<<(E + 255) / 256, 256>>>(el0, er0, mbuf, isbuf, srcp, dstp, alpha, E);
    k_gather<2><<<numNodes, 256>>>(h0, alpha, b0, rowptr, srcp, x1, 1, 0);

    // layer 1 (H=1)
    k_sgemm<<<dim3(2, (numNodes + 127) / 128), 256>>>(x1, W1, h1, numNodes, 256, 256);
    k_elr<1><<<numNodes, 256>>>(h1, al1, ar1, el1, er1);
    k_stats<1><<<statBlocks, 256>>>(el1, er1, rowptr, srcp, mbuf, isbuf, numNodes);
    k_alpha<1><<<(E + 255) / 256, 256>>>(el1, er1, mbuf, isbuf, srcp, dstp, alpha, E);
    k_gather<1><<<numNodes, 256>>>(h1, alpha, b1, rowptr, srcp, out, 0, 1);
}

// round 3
// speedup vs baseline: 1.6331x; 1.4598x over previous
#include <cuda_runtime.h>
#include <math_constants.h>

static constexpr int NMAX = 50000;
static constexpr int EMAX = 800000;
static constexpr int C    = 256;   // channels per node at every stage

// ---------------- scratch (static device arrays; no allocation) -------------
__device__ float g_h0[(size_t)NMAX * C];
__device__ float g_x1[(size_t)NMAX * C];
__device__ float g_h1[(size_t)NMAX * C];
__device__ float g_el0[NMAX * 2];
__device__ float g_er0[NMAX * 2];
__device__ float g_el1[NMAX];
__device__ float g_er1[NMAX];
__device__ float g_m[NMAX * 2];
__device__ float g_is[NMAX * 2];
__device__ float g_alpha[(size_t)EMAX * 2];
__device__ float g_P0[128 * 2];
__device__ float g_Q0[128 * 2];
__device__ float g_P1[256];
__device__ float g_Q1[256];
__device__ int   g_cnt[NMAX];
__device__ int   g_rowptr[NMAX + 1];
__device__ int   g_cursor[NMAX];
__device__ int   g_srcp[EMAX];   // src id per permuted edge slot
__device__ int   g_dstp[EMAX];   // dst id per permuted edge slot

// ---------------- CSR build -------------------------------------------------
__global__ void k_hist(const int* __restrict__ dst, int E) {
    int i = blockIdx.x * blockDim.x + threadIdx.x;
    if (i < E) atomicAdd(&g_cnt[dst[i]], 1);
}

// single block, 1024 threads: chunked exclusive scan of g_cnt -> rowptr/cursor
__global__ void k_scan(int N) {
    const int T = 1024;
    int tid = threadIdx.x;
    int per = (N + T - 1) / T;
    int begin = tid * per;
    int end   = min(begin + per, N);
    int sum = 0;
    for (int i = begin; i < end; i++) sum += g_cnt[i];
    __shared__ int s[T];
    s[tid] = sum;
    __syncthreads();
    for (int off = 1; off < T; off <<= 1) {
        int v = (tid >= off) ? s[tid - off] : 0;
        __syncthreads();
        s[tid] += v;
        __syncthreads();
    }
    int run = s[tid] - sum;  // exclusive prefix for my chunk
    for (int i = begin; i < end; i++) {
        g_rowptr[i] = run;
        g_cursor[i] = run;
        run += g_cnt[i];
    }
    if (tid == T - 1) g_rowptr[N] = s[T - 1];
}

__global__ void k_scatter(const int* __restrict__ src, const int* __restrict__ dst, int E) {
    int i = blockIdx.x * blockDim.x + threadIdx.x;
    if (i < E) {
        int d = dst[i];
        int p = atomicAdd(&g_cursor[d], 1);
        g_srcp[p] = src[i];
        g_dstp[p] = d;
    }
}

// ---------------- fp32 SGEMM: C[M,N] = A[M,K] @ B[K,N] ----------------------
__global__ void __launch_bounds__(256) k_sgemm(const float* __restrict__ A,
                                               const float* __restrict__ B,
                                               float* __restrict__ Cm,
                                               int M, int N, int K) {
    __shared__ float As[8][128];
    __shared__ float Bs[8][128];
    int tid = threadIdx.x;
    int bn0 = blockIdx.x * 128;
    int m0  = blockIdx.y * 128;
    int ty = tid >> 4, tx = tid & 15;
    int arow = tid >> 1, acol = (tid & 1) * 4;
    int brow = tid >> 5, bcol = (tid & 31) * 4;

    float acc[8][8];
#pragma unroll
    for (int i = 0; i < 8; i++)
#pragma unroll
        for (int j = 0; j < 8; j++) acc[i][j] = 0.f;

    for (int k0 = 0; k0 < K; k0 += 8) {
        int grow = m0 + arow;
        float4 va = make_float4(0.f, 0.f, 0.f, 0.f);
        if (grow < M) va = *(const float4*)(A + (size_t)grow * K + k0 + acol);
        As[acol + 0][arow] = va.x;
        As[acol + 1][arow] = va.y;
        As[acol + 2][arow] = va.z;
        As[acol + 3][arow] = va.w;
        float4 vb = *(const float4*)(B + (size_t)(k0 + brow) * N + bn0 + bcol);
        *(float4*)&Bs[brow][bcol] = vb;
        __syncthreads();
#pragma unroll
        for (int k = 0; k < 8; k++) {
            float ra[8], rb[8];
#pragma unroll
            for (int i = 0; i < 8; i++) ra[i] = As[k][ty * 8 + i];
#pragma unroll
            for (int j = 0; j < 8; j++) rb[j] = Bs[k][tx * 8 + j];
#pragma unroll
            for (int i = 0; i < 8; i++)
#pragma unroll
                for (int j = 0; j < 8; j++)
                    acc[i][j] = fmaf(ra[i], rb[j], acc[i][j]);
        }
        __syncthreads();
    }
#pragma unroll
    for (int i = 0; i < 8; i++) {
        int row = m0 + ty * 8 + i;
        if (row < M) {
            float4 o1 = make_float4(acc[i][0], acc[i][1], acc[i][2], acc[i][3]);
            float4 o2 = make_float4(acc[i][4], acc[i][5], acc[i][6], acc[i][7]);
            *(float4*)(Cm + (size_t)row * N + bn0 + tx * 8)     = o1;
            *(float4*)(Cm + (size_t)row * N + bn0 + tx * 8 + 4) = o2;
        }
    }
}

// ---------------- projected attention vectors P=W.al, Q=W.ar ----------------
// W: [K, 256]; al/ar flattened [256] with head = col/ (256/H).
// One block per row d: P[d*H+h] = sum_{c in head h} W[d,c]*al[c]
template <int H>
__global__ void __launch_bounds__(256) k_WP(const float* __restrict__ W,
                                            const float* __restrict__ al,
                                            const float* __restrict__ ar,
                                            float* __restrict__ P,
                                            float* __restrict__ Q) {
    constexpr int G = 256 / H;
    int d = blockIdx.x, t = threadIdx.x;
    float v = W[(size_t)d * 256 + t];
    __shared__ float sl[256];
    __shared__ float sr[256];
    sl[t] = v * al[t];
    sr[t] = v * ar[t];
    __syncthreads();
#pragma unroll
    for (int off = G / 2; off > 0; off >>= 1) {
        if ((t % G) < off) {
            sl[t] += sl[t + off];
            sr[t] += sr[t + off];
        }
        __syncthreads();
    }
    if ((t % G) == 0) {
        P[d * H + t / G] = sl[t];
        Q[d * H + t / G] = sr[t];
    }
}

// ---------------- el/er via GEMV: el[n,h] = x[n,:] @ P[:,h] ------------------
// warp per node; K = input feature dim (128 or 256)
template <int H, int K>
__global__ void __launch_bounds__(256) k_elr_gemv(const float* __restrict__ x,
                                                  const float* __restrict__ P,
                                                  const float* __restrict__ Q,
                                                  float* __restrict__ el,
                                                  float* __restrict__ er,
                                                  int N) {
    int warp = (blockIdx.x * blockDim.x + threadIdx.x) >> 5;
    int lane = threadIdx.x & 31;
    if (warp >= N) return;
    const float* xr = x + (size_t)warp * K;
    float accl[H], accr[H];
#pragma unroll
    for (int h = 0; h < H; h++) { accl[h] = 0.f; accr[h] = 0.f; }
#pragma unroll
    for (int j = 0; j < K / 32; j++) {
        int d = lane + 32 * j;
        float xv = xr[d];
#pragma unroll
        for (int h = 0; h < H; h++) {
            accl[h] = fmaf(xv, P[d * H + h], accl[h]);
            accr[h] = fmaf(xv, Q[d * H + h], accr[h]);
        }
    }
#pragma unroll
    for (int h = 0; h < H; h++) {
#pragma unroll
        for (int o = 16; o > 0; o >>= 1) {
            accl[h] += __shfl_xor_sync(0xffffffffu, accl[h], o);
            accr[h] += __shfl_xor_sync(0xffffffffu, accr[h], o);
        }
    }
    if (lane == 0) {
#pragma unroll
        for (int h = 0; h < H; h++) {
            el[warp * H + h] = accl[h];
            er[warp * H + h] = accr[h];
        }
    }
}

// ---------------- phase A: per-node softmax stats (warp per node) -----------
template <int H>
__global__ void __launch_bounds__(256) k_stats(const float* __restrict__ el,
                                               const float* __restrict__ er,
                                               const int* __restrict__ rowptr,
                                               const int* __restrict__ srcp,
                                               float* __restrict__ mOut,
                                               float* __restrict__ isOut,
                                               int N) {
    int warp = (blockIdx.x * blockDim.x + threadIdx.x) >> 5;
    int lane = threadIdx.x & 31;
    if (warp >= N) return;
    int n = warp;
    int start = rowptr[n];
    int deg   = rowptr[n + 1] - start;

    float ern[H];
#pragma unroll
    for (int h = 0; h < H; h++) ern[h] = er[n * H + h];

    float m[H], s[H];
#pragma unroll
    for (int h = 0; h < H; h++) { m[h] = -1e30f; s[h] = 0.f; }

    for (int i = lane; i < deg; i += 32) {
        int sid = srcp[start + i];
#pragma unroll
        for (int h = 0; h < H; h++) {
            float v = el[sid * H + h] + ern[h];
            v = v > 0.f ? v : 0.2f * v;
            float mn = fmaxf(m[h], v);
            s[h] = s[h] * __expf(m[h] - mn) + __expf(v - mn);
            m[h] = mn;
        }
    }
#pragma unroll
    for (int h = 0; h < H; h++) {
#pragma unroll
        for (int o = 16; o > 0; o >>= 1) {
            float m2 = __shfl_xor_sync(0xffffffffu, m[h], o);
            float s2 = __shfl_xor_sync(0xffffffffu, s[h], o);
            float mn = fmaxf(m[h], m2);
            s[h] = s[h] * __expf(m[h] - mn) + s2 * __expf(m2 - mn);
            m[h] = mn;
        }
    }
    if (lane == 0) {
#pragma unroll
        for (int h = 0; h < H; h++) {
            mOut[n * H + h]  = m[h];
            isOut[n * H + h] = s[h] > 0.f ? 1.f / s[h] : 0.f;
        }
    }
}

// ---------------- phase B: per-edge alpha (permuted order) ------------------
template <int H>
__global__ void __launch_bounds__(256) k_alpha(const float* __restrict__ el,
                                               const float* __restrict__ er,
                                               const float* __restrict__ mIn,
                                               const float* __restrict__ isIn,
                                               const int* __restrict__ srcp,
                                               const int* __restrict__ dstp,
                                               float* __restrict__ alpha,
                                               int E) {
    int i = blockIdx.x * blockDim.x + threadIdx.x;
    if (i >= E) return;
    int sid = srcp[i];
    int d   = dstp[i];
#pragma unroll
    for (int h = 0; h < H; h++) {
        float v = el[sid * H + h] + er[d * H + h];
        v = v > 0.f ? v : 0.2f * v;
        alpha[(size_t)i * H + h] = __expf(v - mIn[d * H + h]) * isIn[d * H + h];
    }
}

// ---------------- phase C: aggregation gather --------------------------------
// 64 threads per node (float4 per thread), 4 nodes per 256-thread block.
template <int H>
__global__ void __launch_bounds__(256) k_gather(const float4* __restrict__ hmat4,
                                                const float* __restrict__ alpha,
                                                const float4* __restrict__ bias4,
                                                const int* __restrict__ rowptr,
                                                const int* __restrict__ srcp,
                                                float4* __restrict__ out4,
                                                int N, int relu_out, int zero0) {
    int g = threadIdx.x >> 6;   // group within block
    int t = threadIdx.x & 63;   // thread within group (owns channels 4t..4t+3)
    int n = blockIdx.x * 4 + g;
    if (n >= N) return;
    int start = rowptr[n];
    int deg   = rowptr[n + 1] - start;
    int hof = (H == 2) ? (t >> 5) : 0;   // head of channel 4t

    float4 acc = make_float4(0.f, 0.f, 0.f, 0.f);
    int i = 0;
    for (; i + 4 <= deg; i += 4) {
        int idx = start + i;
        int s0 = srcp[idx + 0];
        int s1 = srcp[idx + 1];
        int s2 = srcp[idx + 2];
        int s3 = srcp[idx + 3];
        float a0 = alpha[(size_t)(idx + 0) * H + hof];
        float a1 = alpha[(size_t)(idx + 1) * H + hof];
        float a2 = alpha[(size_t)(idx + 2) * H + hof];
        float a3 = alpha[(size_t)(idx + 3) * H + hof];
        float4 v0 = hmat4[(size_t)s0 * 64 + t];
        float4 v1 = hmat4[(size_t)s1 * 64 + t];
        float4 v2 = hmat4[(size_t)s2 * 64 + t];
        float4 v3 = hmat4[(size_t)s3 * 64 + t];
        acc.x = fmaf(a0, v0.x, acc.x); acc.y = fmaf(a0, v0.y, acc.y);
        acc.z = fmaf(a0, v0.z, acc.z); acc.w = fmaf(a0, v0.w, acc.w);
        acc.x = fmaf(a1, v1.x, acc.x); acc.y = fmaf(a1, v1.y, acc.y);
        acc.z = fmaf(a1, v1.z, acc.z); acc.w = fmaf(a1, v1.w, acc.w);
        acc.x = fmaf(a2, v2.x, acc.x); acc.y = fmaf(a2, v2.y, acc.y);
        acc.z = fmaf(a2, v2.z, acc.z); acc.w = fmaf(a2, v2.w, acc.w);
        acc.x = fmaf(a3, v3.x, acc.x); acc.y = fmaf(a3, v3.y, acc.y);
        acc.z = fmaf(a3, v3.z, acc.z); acc.w = fmaf(a3, v3.w, acc.w);
    }
    for (; i < deg; i++) {
        int idx = start + i;
        int s = srcp[idx];
        float a = alpha[(size_t)idx * H + hof];
        float4 v = hmat4[(size_t)s * 64 + t];
        acc.x = fmaf(a, v.x, acc.x); acc.y = fmaf(a, v.y, acc.y);
        acc.z = fmaf(a, v.z, acc.z); acc.w = fmaf(a, v.w, acc.w);
    }

    float4 b = bias4[t];
    acc.x += b.x; acc.y += b.y; acc.z += b.z; acc.w += b.w;
    if (relu_out) {
        acc.x = fmaxf(acc.x, 0.f); acc.y = fmaxf(acc.y, 0.f);
        acc.z = fmaxf(acc.z, 0.f); acc.w = fmaxf(acc.w, 0.f);
    }
    if (zero0 && n == 0) acc = make_float4(0.f, 0.f, 0.f, 0.f);
    out4[(size_t)n * 64 + t] = acc;
}

// ---------------- host launcher ----------------------------------------------
extern "C" void kernel_launch(void* const* d_in, const int* in_sizes, int n_in,
                              void* d_out, int out_size) {
    const float* emb = (const float*)d_in[0];
    const float* W0  = (const float*)d_in[1];
    const float* al0 = (const float*)d_in[2];
    const float* ar0 = (const float*)d_in[3];
    const float* b0  = (const float*)d_in[4];
    const float* W1  = (const float*)d_in[5];
    const float* al1 = (const float*)d_in[6];
    const float* ar1 = (const float*)d_in[7];
    const float* b1  = (const float*)d_in[8];
    const int*   src = (const int*)d_in[9];
    const int*   dst = (const int*)d_in[10];
    float* out = (float*)d_out;

    int numNodes = in_sizes[0] / 128;   // 50000
    int E        = in_sizes[9];         // 800000

    float *h0, *x1, *h1, *el0, *er0, *el1, *er1, *mbuf, *isbuf, *alpha;
    float *P0, *Q0, *P1, *Q1;
    int *cnt, *rowptr, *srcp, *dstp;
    cudaGetSymbolAddress((void**)&h0, g_h0);
    cudaGetSymbolAddress((void**)&x1, g_x1);
    cudaGetSymbolAddress((void**)&h1, g_h1);
    cudaGetSymbolAddress((void**)&el0, g_el0);
    cudaGetSymbolAddress((void**)&er0, g_er0);
    cudaGetSymbolAddress((void**)&el1, g_el1);
    cudaGetSymbolAddress((void**)&er1, g_er1);
    cudaGetSymbolAddress((void**)&mbuf, g_m);
    cudaGetSymbolAddress((void**)&isbuf, g_is);
    cudaGetSymbolAddress((void**)&alpha, g_alpha);
    cudaGetSymbolAddress((void**)&P0, g_P0);
    cudaGetSymbolAddress((void**)&Q0, g_Q0);
    cudaGetSymbolAddress((void**)&P1, g_P1);
    cudaGetSymbolAddress((void**)&Q1, g_Q1);
    cudaGetSymbolAddress((void**)&cnt, g_cnt);
    cudaGetSymbolAddress((void**)&rowptr, g_rowptr);
    cudaGetSymbolAddress((void**)&srcp, g_srcp);
    cudaGetSymbolAddress((void**)&dstp, g_dstp);

    // CSR build (shared by both layers)
    cudaMemsetAsync(cnt, 0, numNodes * sizeof(int));
    k_hist<<<(E + 255) / 256, 256>>>(dst, E);
    k_scan<<<1, 1024>>>(numNodes);
    k_scatter<<<(E + 255) / 256, 256>>>(src, dst, E);

    // attention projection vectors (tiny)
    k_WP<2><<<128, 256>>>(W0, al0, ar0, P0, Q0);
    k_WP<1><<<256, 256>>>(W1, al1, ar1, P1, Q1);

    int warpBlocks = (numNodes * 32 + 255) / 256;
    int gatherBlocks = (numNodes + 3) / 4;

    // layer 0 (H=2): el/er from emb directly (independent of sgemm)
    k_elr_gemv<2, 128><<<warpBlocks, 256>>>(emb, P0, Q0, el0, er0, numNodes);
    k_sgemm<<<dim3(2, (numNodes + 127) / 128), 256>>>(emb, W0, h0, numNodes, 256, 128);
    k_stats<2><<<warpBlocks, 256>>>(el0, er0, rowptr, srcp, mbuf, isbuf, numNodes);
    k_alpha<2><<<(E + 255) / 256, 256>>>(el0, er0, mbuf, isbuf, srcp, dstp, alpha, E);
    k_gather<2><<<gatherBlocks, 256>>>((const float4*)h0, alpha, (const float4*)b0,
                                       rowptr, srcp, (float4*)x1, numNodes, 1, 0);

    // layer 1 (H=1)
    k_elr_gemv<1, 256><<<warpBlocks, 256>>>(x1, P1, Q1, el1, er1, numNodes);
    k_sgemm<<<dim3(2, (numNodes + 127) / 128), 256>>>(x1, W1, h1, numNodes, 256, 256);
    k_stats<1><<<warpBlocks, 256>>>(el1, er1, rowptr, srcp, mbuf, isbuf, numNodes);
    k_alpha<1><<<(E + 255) / 256, 256>>>(el1, er1, mbuf, isbuf, srcp, dstp, alpha, E);
    k_gather<1><<<gatherBlocks, 256>>>((const float4*)h1, alpha, (const float4*)b1,
                                       rowptr, srcp, (float4*)out, numNodes, 0, 1);
}

// round 5
// speedup vs baseline: 2.1689x; 1.3281x over previous
#include <cuda_runtime.h>
#include <cuda_bf16.h>
#include <math_constants.h>
#include <cstdint>

static constexpr int NMAX = 50000;
static constexpr int EMAX = 800000;
static constexpr int C    = 256;   // channels per node at every stage

// ---------------- scratch (static device arrays; no allocation) -------------
__device__ float g_h0[(size_t)NMAX * C];
__device__ float g_x1[(size_t)NMAX * C];
__device__ float g_h1[(size_t)NMAX * C];
__device__ float g_el0[NMAX * 2];
__device__ float g_er0[NMAX * 2];
__device__ float g_el1[NMAX];
__device__ float g_er1[NMAX];
__device__ float g_m[NMAX * 2];
__device__ float g_is[NMAX * 2];
__device__ float g_alpha[(size_t)EMAX * 2];
__device__ float g_P0[128 * 2];
__device__ float g_Q0[128 * 2];
__device__ float g_P1[256];
__device__ float g_Q1[256];
__device__ __align__(16) __nv_bfloat16 g_Bh[256 * 256];   // W^T hi, [N=256][K]
__device__ __align__(16) __nv_bfloat16 g_Bl[256 * 256];   // W^T lo
__device__ int   g_cnt[NMAX];
__device__ int   g_rowptr[NMAX + 1];
__device__ int   g_cursor[NMAX];
__device__ int   g_srcp[EMAX];   // src id per permuted edge slot
__device__ int   g_dstp[EMAX];   // dst id per permuted edge slot

// ---------------- helpers ----------------------------------------------------
__device__ __forceinline__ uint32_t smem_u32(const void* p) {
    uint32_t a;
    asm("{ .reg .u64 t; cvta.to.shared.u64 t, %1; cvt.u32.u64 %0, t; }" : "=r"(a) : "l"(p));
    return a;
}

__device__ __forceinline__ void ldmatrix_x4(uint32_t& r0, uint32_t& r1,
                                            uint32_t& r2, uint32_t& r3, uint32_t addr) {
    asm volatile("ldmatrix.sync.aligned.m8n8.x4.shared.b16 {%0,%1,%2,%3}, [%4];"
                 : "=r"(r0), "=r"(r1), "=r"(r2), "=r"(r3) : "r"(addr));
}
__device__ __forceinline__ void ldmatrix_x2(uint32_t& r0, uint32_t& r1, uint32_t addr) {
    asm volatile("ldmatrix.sync.aligned.m8n8.x2.shared.b16 {%0,%1}, [%2];"
                 : "=r"(r0), "=r"(r1) : "r"(addr));
}
__device__ __forceinline__ void mma_bf16(float* c, const uint32_t* a, const uint32_t* b) {
    asm volatile(
        "mma.sync.aligned.m16n8k16.row.col.f32.bf16.bf16.f32 "
        "{%0,%1,%2,%3}, {%4,%5,%6,%7}, {%8,%9}, {%0,%1,%2,%3};"
        : "+f"(c[0]), "+f"(c[1]), "+f"(c[2]), "+f"(c[3])
        : "r"(a[0]), "r"(a[1]), "r"(a[2]), "r"(a[3]), "r"(b[0]), "r"(b[1]));
}

// ---------------- CSR build -------------------------------------------------
__global__ void k_hist(const int* __restrict__ dst, int E) {
    int i = blockIdx.x * blockDim.x + threadIdx.x;
    if (i < E) atomicAdd(&g_cnt[dst[i]], 1);
}

__global__ void k_scan(int N) {
    const int T = 1024;
    int tid = threadIdx.x;
    int per = (N + T - 1) / T;
    int begin = tid * per;
    int end   = min(begin + per, N);
    int sum = 0;
    for (int i = begin; i < end; i++) sum += g_cnt[i];
    __shared__ int s[T];
    s[tid] = sum;
    __syncthreads();
    for (int off = 1; off < T; off <<= 1) {
        int v = (tid >= off) ? s[tid - off] : 0;
        __syncthreads();
        s[tid] += v;
        __syncthreads();
    }
    int run = s[tid] - sum;
    for (int i = begin; i < end; i++) {
        g_rowptr[i] = run;
        g_cursor[i] = run;
        run += g_cnt[i];
    }
    if (tid == T - 1) g_rowptr[N] = s[T - 1];
}

__global__ void k_scatter(const int* __restrict__ src, const int* __restrict__ dst, int E) {
    int i = blockIdx.x * blockDim.x + threadIdx.x;
    if (i < E) {
        int d = dst[i];
        int p = atomicAdd(&g_cursor[d], 1);
        g_srcp[p] = src[i];
        g_dstp[p] = d;
    }
}

// ---------------- W -> bf16 hi/lo transposed [N=256][K] ----------------------
__global__ void k_wconv(const float* __restrict__ W, __nv_bfloat16* __restrict__ Bh,
                        __nv_bfloat16* __restrict__ Bl, int K) {
    int idx = blockIdx.x * blockDim.x + threadIdx.x;
    if (idx >= 256 * K) return;
    int n = idx / K, k = idx % K;
    float v = W[(size_t)k * 256 + n];
    __nv_bfloat16 h = __float2bfloat16(v);
    float lo = v - __bfloat162float(h);
    Bh[idx] = h;
    Bl[idx] = __float2bfloat16(lo);
}

// ---------------- mma.sync bf16-split GEMM: C[M,256] = A[M,K] @ W[K,256] -----
// CTA: 128 rows x 128 cols; grid (2, ceil(M/128)). 8 warps, warp tile 64x32.
// 3-term split: Ah*Bh + Al*Bh + Ah*Bl, fp32 accumulate.
static constexpr int SA = 40;   // smem row stride in bf16 (80B: conflict-free ldmatrix)

__global__ void __launch_bounds__(256) k_mma_gemm(const float* __restrict__ A,
                                                  const __nv_bfloat16* __restrict__ Bh,
                                                  const __nv_bfloat16* __restrict__ Bl,
                                                  float* __restrict__ Cout,
                                                  int M, int K) {
    __shared__ __align__(16) __nv_bfloat16 sAh[128 * SA];
    __shared__ __align__(16) __nv_bfloat16 sAl[128 * SA];
    __shared__ __align__(16) __nv_bfloat16 sBh[128 * SA];
    __shared__ __align__(16) __nv_bfloat16 sBl[128 * SA];

    int tid = threadIdx.x;
    int lane = tid & 31;
    int wid = tid >> 5;
    int n0 = blockIdx.x * 128;
    int m0 = blockIdx.y * 128;
    int mrow = (wid & 1) * 64;   // warp row origin within CTA tile
    int ncol = (wid >> 1) * 32;  // warp col origin

    float acc[4][4][4];
#pragma unroll
    for (int i = 0; i < 4; i++)
#pragma unroll
        for (int j = 0; j < 4; j++)
#pragma unroll
            for (int q = 0; q < 4; q++) acc[i][j][q] = 0.f;

    int arow = tid >> 1, ahalf = tid & 1;
    bool avalid = (m0 + arow) < M;
    const float* aptr = A + (size_t)(m0 + arow) * K + ahalf * 16;

    uint32_t uAh = smem_u32(sAh), uAl = smem_u32(sAl);
    uint32_t uBh = smem_u32(sBh), uBl = smem_u32(sBl);
    // ldmatrix per-lane byte offsets
    uint32_t a_off = (uint32_t)(mrow + (lane & 15)) * (SA * 2) + (lane >> 4) * 16;
    uint32_t b_off = (uint32_t)(ncol + (lane & 7)) * (SA * 2) + ((lane >> 3) & 1) * 16;

    for (int k0 = 0; k0 < K; k0 += 32) {
        if (k0) __syncthreads();

        // ---- stage A chunk: fp32 -> bf16 hi/lo (128 rows x 32 cols) ----
        {
            const float* ap = aptr + k0;
            int base = arow * SA + ahalf * 16;
#pragma unroll
            for (int j = 0; j < 4; j++) {
                float4 v = make_float4(0.f, 0.f, 0.f, 0.f);
                if (avalid) v = *(const float4*)(ap + j * 4);
                __nv_bfloat162 h01 = __floats2bfloat162_rn(v.x, v.y);
                __nv_bfloat162 h23 = __floats2bfloat162_rn(v.z, v.w);
                float lx = v.x - __bfloat162float(h01.x);
                float ly = v.y - __bfloat162float(h01.y);
                float lz = v.z - __bfloat162float(h23.x);
                float lw = v.w - __bfloat162float(h23.y);
                __nv_bfloat162 l01 = __floats2bfloat162_rn(lx, ly);
                __nv_bfloat162 l23 = __floats2bfloat162_rn(lz, lw);
                int idx = base + j * 4;
                *(__nv_bfloat162*)&sAh[idx]     = h01;
                *(__nv_bfloat162*)&sAh[idx + 2] = h23;
                *(__nv_bfloat162*)&sAl[idx]     = l01;
                *(__nv_bfloat162*)&sAl[idx + 2] = l23;
            }
        }
        // ---- stage B chunk: copy [128 n-rows x 32 k] hi/lo ----
        {
#pragma unroll
            for (int it = 0; it < 2; it++) {
                int u = tid + it * 256;
                int row = u >> 2, seg = u & 3;
                int sidx = row * SA + seg * 8;
                size_t gidx = (size_t)(n0 + row) * K + k0 + seg * 8;
                *(uint4*)&sBh[sidx] = *(const uint4*)&Bh[gidx];
                *(uint4*)&sBl[sidx] = *(const uint4*)&Bl[gidx];
            }
        }
        __syncthreads();

        // ---- 3-term MMA ----
#pragma unroll
        for (int term = 0; term < 3; term++) {
            uint32_t ua = (term == 1) ? uAl : uAh;
            uint32_t ub = (term == 2) ? uBl : uBh;
#pragma unroll
            for (int ks = 0; ks < 2; ks++) {
                uint32_t afrag[4][4];
                uint32_t bfrag[4][2];
#pragma unroll
                for (int mt = 0; mt < 4; mt++)
                    ldmatrix_x4(afrag[mt][0], afrag[mt][1], afrag[mt][2], afrag[mt][3],
                                ua + a_off + (uint32_t)mt * 16 * (SA * 2) + ks * 32);
#pragma unroll
                for (int nt = 0; nt < 4; nt++)
                    ldmatrix_x2(bfrag[nt][0], bfrag[nt][1],
                                ub + b_off + (uint32_t)nt * 8 * (SA * 2) + ks * 32);
#pragma unroll
                for (int mt = 0; mt < 4; mt++)
#pragma unroll
                    for (int nt = 0; nt < 4; nt++)
                        mma_bf16(acc[mt][nt], afrag[mt], bfrag[nt]);
            }
        }
    }

    // ---- epilogue ----
#pragma unroll
    for (int mt = 0; mt < 4; mt++) {
        int r0 = m0 + mrow + mt * 16 + (lane >> 2);
#pragma unroll
        for (int nt = 0; nt < 4; nt++) {
            int col = n0 + ncol + nt * 8 + (lane & 3) * 2;
            if (r0 < M) {
                float2 v = make_float2(acc[mt][nt][0], acc[mt][nt][1]);
                *(float2*)&Cout[(size_t)r0 * 256 + col] = v;
            }
            if (r0 + 8 < M) {
                float2 v = make_float2(acc[mt][nt][2], acc[mt][nt][3]);
                *(float2*)&Cout[(size_t)(r0 + 8) * 256 + col] = v;
            }
        }
    }
}

// ---------------- projected attention vectors P=W.al, Q=W.ar ----------------
template <int H>
__global__ void __launch_bounds__(256) k_WP(const float* __restrict__ W,
                                            const float* __restrict__ al,
                                            const float* __restrict__ ar,
                                            float* __restrict__ P,
                                            float* __restrict__ Q) {
    constexpr int G = 256 / H;
    int d = blockIdx.x, t = threadIdx.x;
    float v = W[(size_t)d * 256 + t];
    __shared__ float sl[256];
    __shared__ float sr[256];
    sl[t] = v * al[t];
    sr[t] = v * ar[t];
    __syncthreads();
#pragma unroll
    for (int off = G / 2; off > 0; off >>= 1) {
        if ((t % G) < off) {
            sl[t] += sl[t + off];
            sr[t] += sr[t + off];
        }
        __syncthreads();
    }
    if ((t % G) == 0) {
        P[d * H + t / G] = sl[t];
        Q[d * H + t / G] = sr[t];
    }
}

// ---------------- el/er via GEMV: el[n,h] = x[n,:] @ P[:,h] ------------------
template <int H, int K>
__global__ void __launch_bounds__(256) k_elr_gemv(const float* __restrict__ x,
                                                  const float* __restrict__ P,
                                                  const float* __restrict__ Q,
                                                  float* __restrict__ el,
                                                  float* __restrict__ er,
                                                  int N) {
    int warp = (blockIdx.x * blockDim.x + threadIdx.x) >> 5;
    int lane = threadIdx.x & 31;
    if (warp >= N) return;
    const float* xr = x + (size_t)warp * K;
    float accl[H], accr[H];
#pragma unroll
    for (int h = 0; h < H; h++) { accl[h] = 0.f; accr[h] = 0.f; }
#pragma unroll
    for (int j = 0; j < K / 32; j++) {
        int d = lane + 32 * j;
        float xv = xr[d];
#pragma unroll
        for (int h = 0; h < H; h++) {
            accl[h] = fmaf(xv, P[d * H + h], accl[h]);
            accr[h] = fmaf(xv, Q[d * H + h], accr[h]);
        }
    }
#pragma unroll
    for (int h = 0; h < H; h++) {
#pragma unroll
        for (int o = 16; o > 0; o >>= 1) {
            accl[h] += __shfl_xor_sync(0xffffffffu, accl[h], o);
            accr[h] += __shfl_xor_sync(0xffffffffu, accr[h], o);
        }
    }
    if (lane == 0) {
#pragma unroll
        for (int h = 0; h < H; h++) {
            el[warp * H + h] = accl[h];
            er[warp * H + h] = accr[h];
        }
    }
}

// ---------------- phase A: per-node softmax stats (warp per node) -----------
template <int H>
__global__ void __launch_bounds__(256) k_stats(const float* __restrict__ el,
                                               const float* __restrict__ er,
                                               const int* __restrict__ rowptr,
                                               const int* __restrict__ srcp,
                                               float* __restrict__ mOut,
                                               float* __restrict__ isOut,
                                               int N) {
    int warp = (blockIdx.x * blockDim.x + threadIdx.x) >> 5;
    int lane = threadIdx.x & 31;
    if (warp >= N) return;
    int n = warp;
    int start = rowptr[n];
    int deg   = rowptr[n + 1] - start;

    float ern[H];
#pragma unroll
    for (int h = 0; h < H; h++) ern[h] = er[n * H + h];

    float m[H], s[H];
#pragma unroll
    for (int h = 0; h < H; h++) { m[h] = -1e30f; s[h] = 0.f; }

    for (int i = lane; i < deg; i += 32) {
        int sid = srcp[start + i];
#pragma unroll
        for (int h = 0; h < H; h++) {
            float v = el[sid * H + h] + ern[h];
            v = v > 0.f ? v : 0.2f * v;
            float mn = fmaxf(m[h], v);
            s[h] = s[h] * __expf(m[h] - mn) + __expf(v - mn);
            m[h] = mn;
        }
    }
#pragma unroll
    for (int h = 0; h < H; h++) {
#pragma unroll
        for (int o = 16; o > 0; o >>= 1) {
            float m2 = __shfl_xor_sync(0xffffffffu, m[h], o);
            float s2 = __shfl_xor_sync(0xffffffffu, s[h], o);
            float mn = fmaxf(m[h], m2);
            s[h] = s[h] * __expf(m[h] - mn) + s2 * __expf(m2 - mn);
            m[h] = mn;
        }
    }
    if (lane == 0) {
#pragma unroll
        for (int h = 0; h < H; h++) {
            mOut[n * H + h]  = m[h];
            isOut[n * H + h] = s[h] > 0.f ? 1.f / s[h] : 0.f;
        }
    }
}

// ---------------- phase B: per-edge alpha (permuted order) ------------------
template <int H>
__global__ void __launch_bounds__(256) k_alpha(const float* __restrict__ el,
                                               const float* __restrict__ er,
                                               const float* __restrict__ mIn,
                                               const float* __restrict__ isIn,
                                               const int* __restrict__ srcp,
                                               const int* __restrict__ dstp,
                                               float* __restrict__ alpha,
                                               int E) {
    int i = blockIdx.x * blockDim.x + threadIdx.x;
    if (i >= E) return;
    int sid = srcp[i];
    int d   = dstp[i];
#pragma unroll
    for (int h = 0; h < H; h++) {
        float v = el[sid * H + h] + er[d * H + h];
        v = v > 0.f ? v : 0.2f * v;
        alpha[(size_t)i * H + h] = __expf(v - mIn[d * H + h]) * isIn[d * H + h];
    }
}

// ---------------- phase C: aggregation gather --------------------------------
template <int H>
__global__ void __launch_bounds__(256) k_gather(const float4* __restrict__ hmat4,
                                                const float* __restrict__ alpha,
                                                const float4* __restrict__ bias4,
                                                const int* __restrict__ rowptr,
                                                const int* __restrict__ srcp,
                                                float4* __restrict__ out4,
                                                int N, int relu_out, int zero0) {
    int g = threadIdx.x >> 6;
    int t = threadIdx.x & 63;
    int n = blockIdx.x * 4 + g;
    if (n >= N) return;
    int start = rowptr[n];
    int deg   = rowptr[n + 1] - start;
    int hof = (H == 2) ? (t >> 5) : 0;

    float4 acc = make_float4(0.f, 0.f, 0.f, 0.f);
    int i = 0;
    for (; i + 4 <= deg; i += 4) {
        int idx = start + i;
        int s0 = srcp[idx + 0];
        int s1 = srcp[idx + 1];
        int s2 = srcp[idx + 2];
        int s3 = srcp[idx + 3];
        float a0 = alpha[(size_t)(idx + 0) * H + hof];
        float a1 = alpha[(size_t)(idx + 1) * H + hof];
        float a2 = alpha[(size_t)(idx + 2) * H + hof];
        float a3 = alpha[(size_t)(idx + 3) * H + hof];
        float4 v0 = hmat4[(size_t)s0 * 64 + t];
        float4 v1 = hmat4[(size_t)s1 * 64 + t];
        float4 v2 = hmat4[(size_t)s2 * 64 + t];
        float4 v3 = hmat4[(size_t)s3 * 64 + t];
        acc.x = fmaf(a0, v0.x, acc.x); acc.y = fmaf(a0, v0.y, acc.y);
        acc.z = fmaf(a0, v0.z, acc.z); acc.w = fmaf(a0, v0.w, acc.w);
        acc.x = fmaf(a1, v1.x, acc.x); acc.y = fmaf(a1, v1.y, acc.y);
        acc.z = fmaf(a1, v1.z, acc.z); acc.w = fmaf(a1, v1.w, acc.w);
        acc.x = fmaf(a2, v2.x, acc.x); acc.y = fmaf(a2, v2.y, acc.y);
        acc.z = fmaf(a2, v2.z, acc.z); acc.w = fmaf(a2, v2.w, acc.w);
        acc.x = fmaf(a3, v3.x, acc.x); acc.y = fmaf(a3, v3.y, acc.y);
        acc.z = fmaf(a3, v3.z, acc.z); acc.w = fmaf(a3, v3.w, acc.w);
    }
    for (; i < deg; i++) {
        int idx = start + i;
        int s = srcp[idx];
        float a = alpha[(size_t)idx * H + hof];
        float4 v = hmat4[(size_t)s * 64 + t];
        acc.x = fmaf(a, v.x, acc.x); acc.y = fmaf(a, v.y, acc.y);
        acc.z = fmaf(a, v.z, acc.z); acc.w = fmaf(a, v.w, acc.w);
    }

    float4 b = bias4[t];
    acc.x += b.x; acc.y += b.y; acc.z += b.z; acc.w += b.w;
    if (relu_out) {
        acc.x = fmaxf(acc.x, 0.f); acc.y = fmaxf(acc.y, 0.f);
        acc.z = fmaxf(acc.z, 0.f); acc.w = fmaxf(acc.w, 0.f);
    }
    if (zero0 && n == 0) acc = make_float4(0.f, 0.f, 0.f, 0.f);
    out4[(size_t)n * 64 + t] = acc;
}

// ---------------- host launcher ----------------------------------------------
extern "C" void kernel_launch(void* const* d_in, const int* in_sizes, int n_in,
                              void* d_out, int out_size) {
    const float* emb = (const float*)d_in[0];
    const float* W0  = (const float*)d_in[1];
    const float* al0 = (const float*)d_in[2];
    const float* ar0 = (const float*)d_in[3];
    const float* b0  = (const float*)d_in[4];
    const float* W1  = (const float*)d_in[5];
    const float* al1 = (const float*)d_in[6];
    const float* ar1 = (const float*)d_in[7];
    const float* b1  = (const float*)d_in[8];
    const int*   src = (const int*)d_in[9];
    const int*   dst = (const int*)d_in[10];
    float* out = (float*)d_out;

    int numNodes = in_sizes[0] / 128;   // 50000
    int E        = in_sizes[9];         // 800000

    float *h0, *x1, *h1, *el0, *er0, *el1, *er1, *mbuf, *isbuf, *alpha;
    float *P0, *Q0, *P1, *Q1;
    __nv_bfloat16 *Bh, *Bl;
    int *cnt, *rowptr, *srcp, *dstp;
    cudaGetSymbolAddress((void**)&h0, g_h0);
    cudaGetSymbolAddress((void**)&x1, g_x1);
    cudaGetSymbolAddress((void**)&h1, g_h1);
    cudaGetSymbolAddress((void**)&el0, g_el0);
    cudaGetSymbolAddress((void**)&er0, g_er0);
    cudaGetSymbolAddress((void**)&el1, g_el1);
    cudaGetSymbolAddress((void**)&er1, g_er1);
    cudaGetSymbolAddress((void**)&mbuf, g_m);
    cudaGetSymbolAddress((void**)&isbuf, g_is);
    cudaGetSymbolAddress((void**)&alpha, g_alpha);
    cudaGetSymbolAddress((void**)&P0, g_P0);
    cudaGetSymbolAddress((void**)&Q0, g_Q0);
    cudaGetSymbolAddress((void**)&P1, g_P1);
    cudaGetSymbolAddress((void**)&Q1, g_Q1);
    cudaGetSymbolAddress((void**)&Bh, g_Bh);
    cudaGetSymbolAddress((void**)&Bl, g_Bl);
    cudaGetSymbolAddress((void**)&cnt, g_cnt);
    cudaGetSymbolAddress((void**)&rowptr, g_rowptr);
    cudaGetSymbolAddress((void**)&srcp, g_srcp);
    cudaGetSymbolAddress((void**)&dstp, g_dstp);

    // CSR build (shared by both layers)
    cudaMemsetAsync(cnt, 0, numNodes * sizeof(int));
    k_hist<<<(E + 255) / 256, 256>>>(dst, E);
    k_scan<<<1, 1024>>>(numNodes);
    k_scatter<<<(E + 255) / 256, 256>>>(src, dst, E);

    // attention projection vectors (tiny)
    k_WP<2><<<128, 256>>>(W0, al0, ar0, P0, Q0);
    k_WP<1><<<256, 256>>>(W1, al1, ar1, P1, Q1);

    int warpBlocks = (numNodes * 32 + 255) / 256;
    int gatherBlocks = (numNodes + 3) / 4;
    dim3 gemmGrid(2, (numNodes + 127) / 128);

    // layer 0 (H=2)
    k_wconv<<<(256 * 128 + 255) / 256, 256>>>(W0, Bh, Bl, 128);
    k_elr_gemv<2, 128><<<warpBlocks, 256>>>(emb, P0, Q0, el0, er0, numNodes);
    k_mma_gemm<<<gemmGrid, 256>>>(emb, Bh, Bl, h0, numNodes, 128);
    k_stats<2><<<warpBlocks, 256>>>(el0, er0, rowptr, srcp, mbuf, isbuf, numNodes);
    k_alpha<2><<<(E + 255) / 256, 256>>>(el0, er0, mbuf, isbuf, srcp, dstp, alpha, E);
    k_gather<2><<<gatherBlocks, 256>>>((const float4*)h0, alpha, (const float4*)b0,
                                       rowptr, srcp, (float4*)x1, numNodes, 1, 0);

    // layer 1 (H=1)
    k_wconv<<<(256 * 256 + 255) / 256, 256>>>(W1, Bh, Bl, 256);
    k_elr_gemv<1, 256><<<warpBlocks, 256>>>(x1, P1, Q1, el1, er1, numNodes);
    k_mma_gemm<<<gemmGrid, 256>>>(x1, Bh, Bl, h1, numNodes, 256);
    k_stats<1><<<warpBlocks, 256>>>(el1, er1, rowptr, srcp, mbuf, isbuf, numNodes);
    k_alpha<1><<<(E + 255) / 256, 256>>>(el1, er1, mbuf, isbuf, srcp, dstp, alpha, E);
    k_gather<1><<<gatherBlocks, 256>>>((const float4*)h1, alpha, (const float4*)b1,
                                       rowptr, srcp, (float4*)out, numNodes, 0, 1);
}

// round 6
// speedup vs baseline: 2.3922x; 1.1029x over previous
#include <cuda_runtime.h>
#include <cuda_bf16.h>
#include <cuda_fp16.h>
#include <math_constants.h>
#include <cstdint>

static constexpr int NMAX = 50000;
static constexpr int EMAX = 800000;
static constexpr int C    = 256;   // channels per node at every stage

// ---------------- scratch (static device arrays; no allocation) -------------
__device__ __align__(16) __half g_hh[(size_t)NMAX * C];   // GEMM output (fp16), gather input
__device__ float g_x1[(size_t)NMAX * C];
__device__ float g_el0[NMAX * 2];
__device__ float g_er0[NMAX * 2];
__device__ float g_el1[NMAX];
__device__ float g_er1[NMAX];
__device__ float g_m[NMAX * 2];
__device__ float g_is[NMAX * 2];
__device__ float g_alpha[(size_t)EMAX * 2];
__device__ float g_P0[128 * 2];
__device__ float g_Q0[128 * 2];
__device__ float g_P1[256];
__device__ float g_Q1[256];
__device__ __align__(16) __nv_bfloat16 g_Bh[256 * 256];   // W^T hi, [N=256][K]
__device__ __align__(16) __nv_bfloat16 g_Bl[256 * 256];   // W^T lo
__device__ int   g_cnt[NMAX];
__device__ int   g_rowptr[NMAX + 1];
__device__ int   g_cursor[NMAX];
__device__ int   g_srcp[EMAX];   // src id per permuted edge slot
__device__ int   g_dstp[EMAX];   // dst id per permuted edge slot

// ---------------- helpers ----------------------------------------------------
__device__ __forceinline__ uint32_t smem_u32(const void* p) {
    uint32_t a;
    asm("{ .reg .u64 t; cvta.to.shared.u64 t, %1; cvt.u32.u64 %0, t; }" : "=r"(a) : "l"(p));
    return a;
}

__device__ __forceinline__ void ldmatrix_x4(uint32_t& r0, uint32_t& r1,
                                            uint32_t& r2, uint32_t& r3, uint32_t addr) {
    asm volatile("ldmatrix.sync.aligned.m8n8.x4.shared.b16 {%0,%1,%2,%3}, [%4];"
                 : "=r"(r0), "=r"(r1), "=r"(r2), "=r"(r3) : "r"(addr));
}
__device__ __forceinline__ void ldmatrix_x2(uint32_t& r0, uint32_t& r1, uint32_t addr) {
    asm volatile("ldmatrix.sync.aligned.m8n8.x2.shared.b16 {%0,%1}, [%2];"
                 : "=r"(r0), "=r"(r1) : "r"(addr));
}
__device__ __forceinline__ void mma_bf16(float* c, const uint32_t* a, const uint32_t* b) {
    asm volatile(
        "mma.sync.aligned.m16n8k16.row.col.f32.bf16.bf16.f32 "
        "{%0,%1,%2,%3}, {%4,%5,%6,%7}, {%8,%9}, {%0,%1,%2,%3};"
        : "+f"(c[0]), "+f"(c[1]), "+f"(c[2]), "+f"(c[3])
        : "r"(a[0]), "r"(a[1]), "r"(a[2]), "r"(a[3]), "r"(b[0]), "r"(b[1]));
}

// ---------------- CSR build -------------------------------------------------
__global__ void k_hist(const int* __restrict__ dst, int E) {
    int i = blockIdx.x * blockDim.x + threadIdx.x;
    if (i < E) atomicAdd(&g_cnt[dst[i]], 1);
}

__global__ void k_scan(int N) {
    const int T = 1024;
    int tid = threadIdx.x;
    int per = (N + T - 1) / T;
    int begin = tid * per;
    int end   = min(begin + per, N);
    int sum = 0;
    for (int i = begin; i < end; i++) sum += g_cnt[i];
    __shared__ int s[T];
    s[tid] = sum;
    __syncthreads();
    for (int off = 1; off < T; off <<= 1) {
        int v = (tid >= off) ? s[tid - off] : 0;
        __syncthreads();
        s[tid] += v;
        __syncthreads();
    }
    int run = s[tid] - sum;
    for (int i = begin; i < end; i++) {
        g_rowptr[i] = run;
        g_cursor[i] = run;
        run += g_cnt[i];
    }
    if (tid == T - 1) g_rowptr[N] = s[T - 1];
}

__global__ void k_scatter(const int* __restrict__ src, const int* __restrict__ dst, int E) {
    int i = blockIdx.x * blockDim.x + threadIdx.x;
    if (i < E) {
        int d = dst[i];
        int p = atomicAdd(&g_cursor[d], 1);
        g_srcp[p] = src[i];
        g_dstp[p] = d;
    }
}

// ---------------- W -> bf16 hi/lo transposed [N=256][K] ----------------------
__global__ void k_wconv(const float* __restrict__ W, __nv_bfloat16* __restrict__ Bh,
                        __nv_bfloat16* __restrict__ Bl, int K) {
    int idx = blockIdx.x * blockDim.x + threadIdx.x;
    if (idx >= 256 * K) return;
    int n = idx / K, k = idx % K;
    float v = W[(size_t)k * 256 + n];
    __nv_bfloat16 h = __float2bfloat16(v);
    float lo = v - __bfloat162float(h);
    Bh[idx] = h;
    Bl[idx] = __float2bfloat16(lo);
}

// ---------------- mma.sync bf16-split GEMM -> fp16 output --------------------
// CTA: 128 rows x 128 cols; grid (2, ceil(M/128)). 8 warps, warp tile 64x32.
// 3-term split: Ah*Bh + Al*Bh + Ah*Bl, fp32 accumulate, fp16 store.
static constexpr int SA = 40;   // smem row stride in bf16 (80B: conflict-free ldmatrix)

__global__ void __launch_bounds__(256) k_mma_gemm(const float* __restrict__ A,
                                                  const __nv_bfloat16* __restrict__ Bh,
                                                  const __nv_bfloat16* __restrict__ Bl,
                                                  __half* __restrict__ Cout,
                                                  int M, int K) {
    __shared__ __align__(16) __nv_bfloat16 sAh[128 * SA];
    __shared__ __align__(16) __nv_bfloat16 sAl[128 * SA];
    __shared__ __align__(16) __nv_bfloat16 sBh[128 * SA];
    __shared__ __align__(16) __nv_bfloat16 sBl[128 * SA];

    int tid = threadIdx.x;
    int lane = tid & 31;
    int wid = tid >> 5;
    int n0 = blockIdx.x * 128;
    int m0 = blockIdx.y * 128;
    int mrow = (wid & 1) * 64;
    int ncol = (wid >> 1) * 32;

    float acc[4][4][4];
#pragma unroll
    for (int i = 0; i < 4; i++)
#pragma unroll
        for (int j = 0; j < 4; j++)
#pragma unroll
            for (int q = 0; q < 4; q++) acc[i][j][q] = 0.f;

    int arow = tid >> 1, ahalf = tid & 1;
    bool avalid = (m0 + arow) < M;
    const float* aptr = A + (size_t)(m0 + arow) * K + ahalf * 16;

    uint32_t uAh = smem_u32(sAh), uAl = smem_u32(sAl);
    uint32_t uBh = smem_u32(sBh), uBl = smem_u32(sBl);
    uint32_t a_off = (uint32_t)(mrow + (lane & 15)) * (SA * 2) + (lane >> 4) * 16;
    uint32_t b_off = (uint32_t)(ncol + (lane & 7)) * (SA * 2) + ((lane >> 3) & 1) * 16;

    for (int k0 = 0; k0 < K; k0 += 32) {
        if (k0) __syncthreads();

        // ---- stage A chunk: fp32 -> bf16 hi/lo (128 rows x 32 cols) ----
        {
            const float* ap = aptr + k0;
            int base = arow * SA + ahalf * 16;
#pragma unroll
            for (int j = 0; j < 4; j++) {
                float4 v = make_float4(0.f, 0.f, 0.f, 0.f);
                if (avalid) v = *(const float4*)(ap + j * 4);
                __nv_bfloat162 h01 = __floats2bfloat162_rn(v.x, v.y);
                __nv_bfloat162 h23 = __floats2bfloat162_rn(v.z, v.w);
                float lx = v.x - __bfloat162float(h01.x);
                float ly = v.y - __bfloat162float(h01.y);
                float lz = v.z - __bfloat162float(h23.x);
                float lw = v.w - __bfloat162float(h23.y);
                __nv_bfloat162 l01 = __floats2bfloat162_rn(lx, ly);
                __nv_bfloat162 l23 = __floats2bfloat162_rn(lz, lw);
                int idx = base + j * 4;
                *(__nv_bfloat162*)&sAh[idx]     = h01;
                *(__nv_bfloat162*)&sAh[idx + 2] = h23;
                *(__nv_bfloat162*)&sAl[idx]     = l01;
                *(__nv_bfloat162*)&sAl[idx + 2] = l23;
            }
        }
        // ---- stage B chunk: copy [128 n-rows x 32 k] hi/lo ----
        {
#pragma unroll
            for (int it = 0; it < 2; it++) {
                int u = tid + it * 256;
                int row = u >> 2, seg = u & 3;
                int sidx = row * SA + seg * 8;
                size_t gidx = (size_t)(n0 + row) * K + k0 + seg * 8;
                *(uint4*)&sBh[sidx] = *(const uint4*)&Bh[gidx];
                *(uint4*)&sBl[sidx] = *(const uint4*)&Bl[gidx];
            }
        }
        __syncthreads();

        // ---- 3-term MMA ----
#pragma unroll
        for (int term = 0; term < 3; term++) {
            uint32_t ua = (term == 1) ? uAl : uAh;
            uint32_t ub = (term == 2) ? uBl : uBh;
#pragma unroll
            for (int ks = 0; ks < 2; ks++) {
                uint32_t afrag[4][4];
                uint32_t bfrag[4][2];
#pragma unroll
                for (int mt = 0; mt < 4; mt++)
                    ldmatrix_x4(afrag[mt][0], afrag[mt][1], afrag[mt][2], afrag[mt][3],
                                ua + a_off + (uint32_t)mt * 16 * (SA * 2) + ks * 32);
#pragma unroll
                for (int nt = 0; nt < 4; nt++)
                    ldmatrix_x2(bfrag[nt][0], bfrag[nt][1],
                                ub + b_off + (uint32_t)nt * 8 * (SA * 2) + ks * 32);
#pragma unroll
                for (int mt = 0; mt < 4; mt++)
#pragma unroll
                    for (int nt = 0; nt < 4; nt++)
                        mma_bf16(acc[mt][nt], afrag[mt], bfrag[nt]);
            }
        }
    }

    // ---- epilogue: fp32 acc -> fp16 store ----
#pragma unroll
    for (int mt = 0; mt < 4; mt++) {
        int r0 = m0 + mrow + mt * 16 + (lane >> 2);
#pragma unroll
        for (int nt = 0; nt < 4; nt++) {
            int col = n0 + ncol + nt * 8 + (lane & 3) * 2;
            if (r0 < M) {
                __half2 v = __floats2half2_rn(acc[mt][nt][0], acc[mt][nt][1]);
                *(__half2*)&Cout[(size_t)r0 * 256 + col] = v;
            }
            if (r0 + 8 < M) {
                __half2 v = __floats2half2_rn(acc[mt][nt][2], acc[mt][nt][3]);
                *(__half2*)&Cout[(size_t)(r0 + 8) * 256 + col] = v;
            }
        }
    }
}

// ---------------- projected attention vectors P=W.al, Q=W.ar ----------------
template <int H>
__global__ void __launch_bounds__(256) k_WP(const float* __restrict__ W,
                                            const float* __restrict__ al,
                                            const float* __restrict__ ar,
                                            float* __restrict__ P,
                                            float* __restrict__ Q) {
    constexpr int G = 256 / H;
    int d = blockIdx.x, t = threadIdx.x;
    float v = W[(size_t)d * 256 + t];
    __shared__ float sl[256];
    __shared__ float sr[256];
    sl[t] = v * al[t];
    sr[t] = v * ar[t];
    __syncthreads();
#pragma unroll
    for (int off = G / 2; off > 0; off >>= 1) {
        if ((t % G) < off) {
            sl[t] += sl[t + off];
            sr[t] += sr[t + off];
        }
        __syncthreads();
    }
    if ((t % G) == 0) {
        P[d * H + t / G] = sl[t];
        Q[d * H + t / G] = sr[t];
    }
}

// ---------------- el/er via GEMV: el[n,h] = x[n,:] @ P[:,h] ------------------
template <int H, int K>
__global__ void __launch_bounds__(256) k_elr_gemv(const float* __restrict__ x,
                                                  const float* __restrict__ P,
                                                  const float* __restrict__ Q,
                                                  float* __restrict__ el,
                                                  float* __restrict__ er,
                                                  int N) {
    int warp = (blockIdx.x * blockDim.x + threadIdx.x) >> 5;
    int lane = threadIdx.x & 31;
    if (warp >= N) return;
    const float* xr = x + (size_t)warp * K;
    float accl[H], accr[H];
#pragma unroll
    for (int h = 0; h < H; h++) { accl[h] = 0.f; accr[h] = 0.f; }
#pragma unroll
    for (int j = 0; j < K / 32; j++) {
        int d = lane + 32 * j;
        float xv = xr[d];
#pragma unroll
        for (int h = 0; h < H; h++) {
            accl[h] = fmaf(xv, P[d * H + h], accl[h]);
            accr[h] = fmaf(xv, Q[d * H + h], accr[h]);
        }
    }
#pragma unroll
    for (int h = 0; h < H; h++) {
#pragma unroll
        for (int o = 16; o > 0; o >>= 1) {
            accl[h] += __shfl_xor_sync(0xffffffffu, accl[h], o);
            accr[h] += __shfl_xor_sync(0xffffffffu, accr[h], o);
        }
    }
    if (lane == 0) {
#pragma unroll
        for (int h = 0; h < H; h++) {
            el[warp * H + h] = accl[h];
            er[warp * H + h] = accr[h];
        }
    }
}

// ---------------- phase A: per-node softmax stats (warp per node) -----------
template <int H>
__global__ void __launch_bounds__(256) k_stats(const float* __restrict__ el,
                                               const float* __restrict__ er,
                                               const int* __restrict__ rowptr,
                                               const int* __restrict__ srcp,
                                               float* __restrict__ mOut,
                                               float* __restrict__ isOut,
                                               int N) {
    int warp = (blockIdx.x * blockDim.x + threadIdx.x) >> 5;
    int lane = threadIdx.x & 31;
    if (warp >= N) return;
    int n = warp;
    int start = rowptr[n];
    int deg   = rowptr[n + 1] - start;

    float ern[H];
#pragma unroll
    for (int h = 0; h < H; h++) ern[h] = er[n * H + h];

    float m[H], s[H];
#pragma unroll
    for (int h = 0; h < H; h++) { m[h] = -1e30f; s[h] = 0.f; }

    for (int i = lane; i < deg; i += 32) {
        int sid = srcp[start + i];
#pragma unroll
        for (int h = 0; h < H; h++) {
            float v = el[sid * H + h] + ern[h];
            v = v > 0.f ? v : 0.2f * v;
            float mn = fmaxf(m[h], v);
            s[h] = s[h] * __expf(m[h] - mn) + __expf(v - mn);
            m[h] = mn;
        }
    }
#pragma unroll
    for (int h = 0; h < H; h++) {
#pragma unroll
        for (int o = 16; o > 0; o >>= 1) {
            float m2 = __shfl_xor_sync(0xffffffffu, m[h], o);
            float s2 = __shfl_xor_sync(0xffffffffu, s[h], o);
            float mn = fmaxf(m[h], m2);
            s[h] = s[h] * __expf(m[h] - mn) + s2 * __expf(m2 - mn);
            m[h] = mn;
        }
    }
    if (lane == 0) {
#pragma unroll
        for (int h = 0; h < H; h++) {
            mOut[n * H + h]  = m[h];
            isOut[n * H + h] = s[h] > 0.f ? 1.f / s[h] : 0.f;
        }
    }
}

// ---------------- phase B: per-edge alpha (permuted order) ------------------
template <int H>
__global__ void __launch_bounds__(256) k_alpha(const float* __restrict__ el,
                                               const float* __restrict__ er,
                                               const float* __restrict__ mIn,
                                               const float* __restrict__ isIn,
                                               const int* __restrict__ srcp,
                                               const int* __restrict__ dstp,
                                               float* __restrict__ alpha,
                                               int E) {
    int i = blockIdx.x * blockDim.x + threadIdx.x;
    if (i >= E) return;
    int sid = srcp[i];
    int d   = dstp[i];
#pragma unroll
    for (int h = 0; h < H; h++) {
        float v = el[sid * H + h] + er[d * H + h];
        v = v > 0.f ? v : 0.2f * v;
        alpha[(size_t)i * H + h] = __expf(v - mIn[d * H + h]) * isIn[d * H + h];
    }
}

// ---------------- phase C: aggregation gather (fp16 messages) ----------------
// 32 threads per node, each owns 8 channels (uint4 = 8 halves); 8 nodes/block.
template <int H>
__global__ void __launch_bounds__(256) k_gather(const uint4* __restrict__ hmat,
                                                const float* __restrict__ alpha,
                                                const float* __restrict__ bias,
                                                const int* __restrict__ rowptr,
                                                const int* __restrict__ srcp,
                                                float* __restrict__ out,
                                                int N, int relu_out, int zero0) {
    int g = threadIdx.x >> 5;
    int t = threadIdx.x & 31;
    int n = blockIdx.x * 8 + g;
    if (n >= N) return;
    int start = rowptr[n];
    int deg   = rowptr[n + 1] - start;
    int hof = (H == 2) ? (t >> 4) : 0;   // head of channels 8t..8t+7

    float acc[8];
#pragma unroll
    for (int q = 0; q < 8; q++) acc[q] = 0.f;

    int i = 0;
    for (; i + 4 <= deg; i += 4) {
        int idx = start + i;
        int s0 = srcp[idx + 0];
        int s1 = srcp[idx + 1];
        int s2 = srcp[idx + 2];
        int s3 = srcp[idx + 3];
        float a0 = alpha[(size_t)(idx + 0) * H + hof];
        float a1 = alpha[(size_t)(idx + 1) * H + hof];
        float a2 = alpha[(size_t)(idx + 2) * H + hof];
        float a3 = alpha[(size_t)(idx + 3) * H + hof];
        uint4 v0 = hmat[(size_t)s0 * 32 + t];
        uint4 v1 = hmat[(size_t)s1 * 32 + t];
        uint4 v2 = hmat[(size_t)s2 * 32 + t];
        uint4 v3 = hmat[(size_t)s3 * 32 + t];
#pragma unroll
        for (int p = 0; p < 4; p++) {
            uint32_t w0 = (&v0.x)[p], w1 = (&v1.x)[p], w2 = (&v2.x)[p], w3 = (&v3.x)[p];
            float2 f0 = __half22float2(*(__half2*)&w0);
            float2 f1 = __half22float2(*(__half2*)&w1);
            float2 f2 = __half22float2(*(__half2*)&w2);
            float2 f3 = __half22float2(*(__half2*)&w3);
            acc[p * 2 + 0] = fmaf(a0, f0.x, acc[p * 2 + 0]);
            acc[p * 2 + 1] = fmaf(a0, f0.y, acc[p * 2 + 1]);
            acc[p * 2 + 0] = fmaf(a1, f1.x, acc[p * 2 + 0]);
            acc[p * 2 + 1] = fmaf(a1, f1.y, acc[p * 2 + 1]);
            acc[p * 2 + 0] = fmaf(a2, f2.x, acc[p * 2 + 0]);
            acc[p * 2 + 1] = fmaf(a2, f2.y, acc[p * 2 + 1]);
            acc[p * 2 + 0] = fmaf(a3, f3.x, acc[p * 2 + 0]);
            acc[p * 2 + 1] = fmaf(a3, f3.y, acc[p * 2 + 1]);
        }
    }
    for (; i < deg; i++) {
        int idx = start + i;
        int s = srcp[idx];
        float a = alpha[(size_t)idx * H + hof];
        uint4 v = hmat[(size_t)s * 32 + t];
#pragma unroll
        for (int p = 0; p < 4; p++) {
            uint32_t w = (&v.x)[p];
            float2 f = __half22float2(*(__half2*)&w);
            acc[p * 2 + 0] = fmaf(a, f.x, acc[p * 2 + 0]);
            acc[p * 2 + 1] = fmaf(a, f.y, acc[p * 2 + 1]);
        }
    }

    float4 bL = *(const float4*)&bias[t * 8];
    float4 bH = *(const float4*)&bias[t * 8 + 4];
    acc[0] += bL.x; acc[1] += bL.y; acc[2] += bL.z; acc[3] += bL.w;
    acc[4] += bH.x; acc[5] += bH.y; acc[6] += bH.z; acc[7] += bH.w;
    if (relu_out) {
#pragma unroll
        for (int q = 0; q < 8; q++) acc[q] = fmaxf(acc[q], 0.f);
    }
    if (zero0 && n == 0) {
#pragma unroll
        for (int q = 0; q < 8; q++) acc[q] = 0.f;
    }
    float* o = out + (size_t)n * 256 + t * 8;
    *(float4*)o       = make_float4(acc[0], acc[1], acc[2], acc[3]);
    *(float4*)(o + 4) = make_float4(acc[4], acc[5], acc[6], acc[7]);
}

// ---------------- host launcher ----------------------------------------------
extern "C" void kernel_launch(void* const* d_in, const int* in_sizes, int n_in,
                              void* d_out, int out_size) {
    const float* emb = (const float*)d_in[0];
    const float* W0  = (const float*)d_in[1];
    const float* al0 = (const float*)d_in[2];
    const float* ar0 = (const float*)d_in[3];
    const float* b0  = (const float*)d_in[4];
    const float* W1  = (const float*)d_in[5];
    const float* al1 = (const float*)d_in[6];
    const float* ar1 = (const float*)d_in[7];
    const float* b1  = (const float*)d_in[8];
    const int*   src = (const int*)d_in[9];
    const int*   dst = (const int*)d_in[10];
    float* out = (float*)d_out;

    int numNodes = in_sizes[0] / 128;   // 50000
    int E        = in_sizes[9];         // 800000

    float *x1, *el0, *er0, *el1, *er1, *mbuf, *isbuf, *alpha;
    float *P0, *Q0, *P1, *Q1;
    __half* hh;
    __nv_bfloat16 *Bh, *Bl;
    int *cnt, *rowptr, *srcp, *dstp;
    cudaGetSymbolAddress((void**)&hh, g_hh);
    cudaGetSymbolAddress((void**)&x1, g_x1);
    cudaGetSymbolAddress((void**)&el0, g_el0);
    cudaGetSymbolAddress((void**)&er0, g_er0);
    cudaGetSymbolAddress((void**)&el1, g_el1);
    cudaGetSymbolAddress((void**)&er1, g_er1);
    cudaGetSymbolAddress((void**)&mbuf, g_m);
    cudaGetSymbolAddress((void**)&isbuf, g_is);
    cudaGetSymbolAddress((void**)&alpha, g_alpha);
    cudaGetSymbolAddress((void**)&P0, g_P0);
    cudaGetSymbolAddress((void**)&Q0, g_Q0);
    cudaGetSymbolAddress((void**)&P1, g_P1);
    cudaGetSymbolAddress((void**)&Q1, g_Q1);
    cudaGetSymbolAddress((void**)&Bh, g_Bh);
    cudaGetSymbolAddress((void**)&Bl, g_Bl);
    cudaGetSymbolAddress((void**)&cnt, g_cnt);
    cudaGetSymbolAddress((void**)&rowptr, g_rowptr);
    cudaGetSymbolAddress((void**)&srcp, g_srcp);
    cudaGetSymbolAddress((void**)&dstp, g_dstp);

    // CSR build (shared by both layers)
    cudaMemsetAsync(cnt, 0, numNodes * sizeof(int));
    k_hist<<<(E + 255) / 256, 256>>>(dst, E);
    k_scan<<<1, 1024>>>(numNodes);
    k_scatter<<<(E + 255) / 256, 256>>>(src, dst, E);

    // attention projection vectors (tiny)
    k_WP<2><<<128, 256>>>(W0, al0, ar0, P0, Q0);
    k_WP<1><<<256, 256>>>(W1, al1, ar1, P1, Q1);

    int warpBlocks = (numNodes * 32 + 255) / 256;
    int gatherBlocks = (numNodes + 7) / 8;
    dim3 gemmGrid(2, (numNodes + 127) / 128);

    // layer 0 (H=2)
    k_wconv<<<(256 * 128 + 255) / 256, 256>>>(W0, Bh, Bl, 128);
    k_elr_gemv<2, 128><<<warpBlocks, 256>>>(emb, P0, Q0, el0, er0, numNodes);
    k_mma_gemm<<<gemmGrid, 256>>>(emb, Bh, Bl, hh, numNodes, 128);
    k_stats<2><<<warpBlocks, 256>>>(el0, er0, rowptr, srcp, mbuf, isbuf, numNodes);
    k_alpha<2><<<(E + 255) / 256, 256>>>(el0, er0, mbuf, isbuf, srcp, dstp, alpha, E);
    k_gather<2><<<gatherBlocks, 256>>>((const uint4*)hh, alpha, b0,
                                       rowptr, srcp, x1, numNodes, 1, 0);

    // layer 1 (H=1)
    k_wconv<<<(256 * 256 + 255) / 256, 256>>>(W1, Bh, Bl, 256);
    k_elr_gemv<1, 256><<<warpBlocks, 256>>>(x1, P1, Q1, el1, er1, numNodes);
    k_mma_gemm<<<gemmGrid, 256>>>(x1, Bh, Bl, hh, numNodes, 256);
    k_stats<1><<<warpBlocks, 256>>>(el1, er1, rowptr, srcp, mbuf, isbuf, numNodes);
    k_alpha<1><<<(E + 255) / 256, 256>>>(el1, er1, mbuf, isbuf, srcp, dstp, alpha, E);
    k_gather<1><<<gatherBlocks, 256>>>((const uint4*)hh, alpha, b1,
                                       rowptr, srcp, out, numNodes, 0, 1);
}